// round 7
// baseline (speedup 1.0000x reference)
#include <cuda_runtime.h>

#define BATCH   32768
#define NCONT   56
#define NB      16
#define NCAT    8
#define NUNIQ   100
#define NCOMP   8
#define TPB     256
#define WARPS   8
#define RPWARP  16           // rows per warp (dual-row lanes: rp and rp+8)
#define RPB     128          // rows per block
#define NCHUNK  14           // 56 features / 4 per chunk
#define RPITCH  80           // staged floats per row (4 features * 20)
#define BUF_F   (RPWARP*RPITCH)   // 1280 floats per warp
#define SEPF    1e-3f
#define T1F     10.0f

#define SCODE_F (WARPS*BUF_F)                   // 10240
#define SMEM_F  (SCODE_F + WARPS*RPWARP*NCAT)   // 11264 floats = 45,056 B

// Stable softplus via fast intrinsics (err << 1e-3 budget; verified 5.8e-8 rel).
__device__ __forceinline__ float sp(float x) {
    float e = __expf(-fabsf(x));
    return fmaxf(x, 0.0f) + __logf(1.0f + e);
}

extern __shared__ float smem[];

__global__ void __launch_bounds__(TPB, 2) k_main(
    const float* __restrict__ B,
    const float* __restrict__ Bcat,
    const float* __restrict__ Wh,  const float* __restrict__ bh,
    const float* __restrict__ Wv,  const float* __restrict__ bv,
    const float* __restrict__ Wic, const float* __restrict__ bic,
    const float* __restrict__ Whc, const float* __restrict__ Wvc,
    const float* __restrict__ Wicc,
    float* __restrict__ out)
{
    const int tid  = threadIdx.x;
    const int wid  = tid >> 5;
    const int lane = tid & 31;
    const int rp   = lane >> 2;        // 0..7
    const int fg   = lane & 3;         // 0..3

    float* sBuf  = smem + wid * BUF_F;
    int*   scode = reinterpret_cast<int*>(smem + SCODE_F) + wid * (RPWARP * NCAT);

    const int row0 = blockIdx.x * RPB + wid * RPWARP;

    // ---- warp-cooperative one-hot scan over 16 rows (coalesced) ----
    {
        const float4* gC = reinterpret_cast<const float4*>(Bcat);
        for (int rr = 0; rr < RPWARP; rr++) {
            const float4* base = gC + (size_t)(row0 + rr) * 200;
            #pragma unroll
            for (int t = 0; t < 7; t++) {
                int j = lane + t * 32;
                if (j < 200) {
                    float4 v = __ldg(base + j);
                    if (v.x > 0.5f || v.y > 0.5f || v.z > 0.5f || v.w > 0.5f) {
                        float vals[4] = {v.x, v.y, v.z, v.w};
                        #pragma unroll
                        for (int q = 0; q < 4; q++) {
                            if (vals[q] > 0.5f) {
                                int pos = j * 4 + q;
                                int f = pos / 100;
                                scode[rr * NCAT + f] = pos - f * 100;
                            }
                        }
                    }
                }
            }
        }
    }
    __syncwarp();

    float hsA[NCOMP], vsA[NCOMP], hsB[NCOMP], vsB[NCOMP];
    #pragma unroll
    for (int c = 0; c < NCOMP; c++) { hsA[c]=0.f; vsA[c]=0.f; hsB[c]=0.f; vsB[c]=0.f; }
    float icA = 0.f, icB = 0.f;

    // ---- categorical gathers: lane covers features {fg, fg+4} x rows {A, B} ----
    #pragma unroll
    for (int cf = 0; cf < 2; cf++) {
        const int f  = fg + cf * 4;
        const int cA = scode[rp * NCAT + f];
        const int cB = scode[(rp + 8) * NCAT + f];
        {
            const int wrow = (f * NUNIQ + cA) * NCOMP;
            float4 a0 = __ldg(reinterpret_cast<const float4*>(Whc + wrow));
            float4 a1 = __ldg(reinterpret_cast<const float4*>(Whc + wrow) + 1);
            float4 b0 = __ldg(reinterpret_cast<const float4*>(Wvc + wrow));
            float4 b1 = __ldg(reinterpret_cast<const float4*>(Wvc + wrow) + 1);
            hsA[0]+=sp(a0.x); hsA[1]+=sp(a0.y); hsA[2]+=sp(a0.z); hsA[3]+=sp(a0.w);
            hsA[4]+=sp(a1.x); hsA[5]+=sp(a1.y); hsA[6]+=sp(a1.z); hsA[7]+=sp(a1.w);
            vsA[0]+=sp(b0.x); vsA[1]+=sp(b0.y); vsA[2]+=sp(b0.z); vsA[3]+=sp(b0.w);
            vsA[4]+=sp(b1.x); vsA[5]+=sp(b1.y); vsA[6]+=sp(b1.z); vsA[7]+=sp(b1.w);
            icA += __ldg(Wicc + f * NUNIQ + cA);
        }
        {
            const int wrow = (f * NUNIQ + cB) * NCOMP;
            float4 a0 = __ldg(reinterpret_cast<const float4*>(Whc + wrow));
            float4 a1 = __ldg(reinterpret_cast<const float4*>(Whc + wrow) + 1);
            float4 b0 = __ldg(reinterpret_cast<const float4*>(Wvc + wrow));
            float4 b1 = __ldg(reinterpret_cast<const float4*>(Wvc + wrow) + 1);
            hsB[0]+=sp(a0.x); hsB[1]+=sp(a0.y); hsB[2]+=sp(a0.z); hsB[3]+=sp(a0.w);
            hsB[4]+=sp(a1.x); hsB[5]+=sp(a1.y); hsB[6]+=sp(a1.z); hsB[7]+=sp(a1.w);
            vsB[0]+=sp(b0.x); vsB[1]+=sp(b0.y); vsB[2]+=sp(b0.z); vsB[3]+=sp(b0.w);
            vsB[4]+=sp(b1.x); vsB[5]+=sp(b1.y); vsB[6]+=sp(b1.z); vsB[7]+=sp(b1.w);
            icB += __ldg(Wicc + f * NUNIQ + cB);
        }
    }

    // ---- staging geometry: iter t covers rows {2t, 2t+1}; phases are bank-rainbow ----
    const int rl = (lane >> 2) & 1;                       // row parity within pair
    const int jj = (lane & 3) + ((lane >> 3) << 2);       // f4 index 0..15 within row-chunk
    const float4* ldgp = reinterpret_cast<const float4*>(B) + (size_t)(row0 + rl) * 224 + jj;
    float* stsp = sBuf + rl * RPITCH + (jj >> 2) * 20 + (jj & 3) * 4;

    float4 nb[8];
    #pragma unroll
    for (int t = 0; t < 8; t++) nb[t] = __ldg(ldgp + t * 448);

    const float* bApos = sBuf + rp * RPITCH + fg * 20;
    const float* bBpos = bApos + 8 * RPITCH;

    for (int ch = 0; ch < NCHUNK; ch++) {
        __syncwarp();
        #pragma unroll
        for (int t = 0; t < 8; t++)
            *reinterpret_cast<float4*>(stsp + t * (2 * RPITCH)) = nb[t];
        __syncwarp();
        if (ch + 1 < NCHUNK) {
            #pragma unroll
            for (int t = 0; t < 8; t++)
                nb[t] = __ldg(ldgp + t * 448 + (ch + 1) * 16);
        }

        const int f = ch * 4 + fg;

        // ---------- H subloop (+ IC) ----------
        {
            float hA[NCOMP], hB[NCOMP];
            #pragma unroll
            for (int c = 0; c < NCOMP; c++) { hA[c] = 0.f; hB[c] = 0.f; }
            const float4* wp   = reinterpret_cast<const float4*>(Wh + f * NCOMP);
            const float*  wicp = Wic + f;
            #pragma unroll
            for (int k4 = 0; k4 < 4; k4++) {
                float4 bA = *reinterpret_cast<const float4*>(bApos + k4 * 4);
                float4 bB = *reinterpret_cast<const float4*>(bBpos + k4 * 4);
                float bAk[4] = {bA.x, bA.y, bA.z, bA.w};
                float bBk[4] = {bB.x, bB.y, bB.z, bB.w};
                #pragma unroll
                for (int kk = 0; kk < 4; kk++) {
                    const int k = k4 * 4 + kk;
                    float4 w0 = __ldg(wp + k * 112);
                    float4 w1 = __ldg(wp + k * 112 + 1);
                    float wic = __ldg(wicp + k * NCONT);
                    const float a = bAk[kk], b = bBk[kk];
                    hA[0]=fmaf(a,w0.x,hA[0]); hA[1]=fmaf(a,w0.y,hA[1]);
                    hA[2]=fmaf(a,w0.z,hA[2]); hA[3]=fmaf(a,w0.w,hA[3]);
                    hA[4]=fmaf(a,w1.x,hA[4]); hA[5]=fmaf(a,w1.y,hA[5]);
                    hA[6]=fmaf(a,w1.z,hA[6]); hA[7]=fmaf(a,w1.w,hA[7]);
                    hB[0]=fmaf(b,w0.x,hB[0]); hB[1]=fmaf(b,w0.y,hB[1]);
                    hB[2]=fmaf(b,w0.z,hB[2]); hB[3]=fmaf(b,w0.w,hB[3]);
                    hB[4]=fmaf(b,w1.x,hB[4]); hB[5]=fmaf(b,w1.y,hB[5]);
                    hB[6]=fmaf(b,w1.z,hB[6]); hB[7]=fmaf(b,w1.w,hB[7]);
                    icA = fmaf(a, wic, icA);
                    icB = fmaf(b, wic, icB);
                }
            }
            #pragma unroll
            for (int c = 0; c < NCOMP; c++) { hsA[c] += sp(hA[c]); hsB[c] += sp(hB[c]); }
        }

        // ---------- V subloop ----------
        {
            float vA[NCOMP], vB[NCOMP];
            #pragma unroll
            for (int c = 0; c < NCOMP; c++) { vA[c] = 0.f; vB[c] = 0.f; }
            const float4* wp = reinterpret_cast<const float4*>(Wv + f * NCOMP);
            #pragma unroll
            for (int k4 = 0; k4 < 4; k4++) {
                float4 bA = *reinterpret_cast<const float4*>(bApos + k4 * 4);
                float4 bB = *reinterpret_cast<const float4*>(bBpos + k4 * 4);
                float bAk[4] = {bA.x, bA.y, bA.z, bA.w};
                float bBk[4] = {bB.x, bB.y, bB.z, bB.w};
                #pragma unroll
                for (int kk = 0; kk < 4; kk++) {
                    const int k = k4 * 4 + kk;
                    float4 w0 = __ldg(wp + k * 112);
                    float4 w1 = __ldg(wp + k * 112 + 1);
                    const float a = bAk[kk], b = bBk[kk];
                    vA[0]=fmaf(a,w0.x,vA[0]); vA[1]=fmaf(a,w0.y,vA[1]);
                    vA[2]=fmaf(a,w0.z,vA[2]); vA[3]=fmaf(a,w0.w,vA[3]);
                    vA[4]=fmaf(a,w1.x,vA[4]); vA[5]=fmaf(a,w1.y,vA[5]);
                    vA[6]=fmaf(a,w1.z,vA[6]); vA[7]=fmaf(a,w1.w,vA[7]);
                    vB[0]=fmaf(b,w0.x,vB[0]); vB[1]=fmaf(b,w0.y,vB[1]);
                    vB[2]=fmaf(b,w0.z,vB[2]); vB[3]=fmaf(b,w0.w,vB[3]);
                    vB[4]=fmaf(b,w1.x,vB[4]); vB[5]=fmaf(b,w1.y,vB[5]);
                    vB[6]=fmaf(b,w1.z,vB[6]); vB[7]=fmaf(b,w1.w,vB[7]);
                }
            }
            #pragma unroll
            for (int c = 0; c < NCOMP; c++) { vsA[c] += sp(vA[c]); vsB[c] += sp(vB[c]); }
        }
    }

    // ---- reduce over the 4 fg lanes (xor 1, 2 stay within the row group) ----
    #pragma unroll
    for (int c = 0; c < NCOMP; c++) {
        hsA[c] += __shfl_xor_sync(0xffffffffu, hsA[c], 1);
        hsA[c] += __shfl_xor_sync(0xffffffffu, hsA[c], 2);
        vsA[c] += __shfl_xor_sync(0xffffffffu, vsA[c], 1);
        vsA[c] += __shfl_xor_sync(0xffffffffu, vsA[c], 2);
        hsB[c] += __shfl_xor_sync(0xffffffffu, hsB[c], 1);
        hsB[c] += __shfl_xor_sync(0xffffffffu, hsB[c], 2);
        vsB[c] += __shfl_xor_sync(0xffffffffu, vsB[c], 1);
        vsB[c] += __shfl_xor_sync(0xffffffffu, vsB[c], 2);
    }
    icA += __shfl_xor_sync(0xffffffffu, icA, 1);
    icA += __shfl_xor_sync(0xffffffffu, icA, 2);
    icB += __shfl_xor_sync(0xffffffffu, icB, 1);
    icB += __shfl_xor_sync(0xffffffffu, icB, 2);

    if (fg == 0) {
        // bias column, shared between the two rows
        #pragma unroll
        for (int c = 0; c < NCOMP; c++) {
            float sbh = sp(__ldg(bh + c));
            float sbv = sp(__ldg(bv + c));
            hsA[c] += sbh; hsB[c] += sbh;
            vsA[c] += sbv; vsB[c] += sbv;
        }
        float bic0 = __ldg(bic);
        icA += bic0; icB += bic0;

        // epilogue for row A
        {
            float2 o[NCOMP + 1];
            o[0] = make_float2(0.0f, icA);
            float cum = 0.0f, xc = icA;
            #pragma unroll
            for (int c = 0; c < NCOMP; c++) {
                cum += hsA[c];
                xc  += (c & 1) ? -vsA[c] : vsA[c];
                o[c + 1] = make_float2(cum + SEPF * (float)(c + 1), xc);
            }
            o[NCOMP].x = fmaxf(o[NCOMP - 1].x + SEPF, T1F);
            float2* op = reinterpret_cast<float2*>(out + (size_t)(row0 + rp) * 2 * (NCOMP + 1));
            #pragma unroll
            for (int j2 = 0; j2 < NCOMP + 1; j2++) op[j2] = o[j2];
        }
        // epilogue for row B
        {
            float2 o[NCOMP + 1];
            o[0] = make_float2(0.0f, icB);
            float cum = 0.0f, xc = icB;
            #pragma unroll
            for (int c = 0; c < NCOMP; c++) {
                cum += hsB[c];
                xc  += (c & 1) ? -vsB[c] : vsB[c];
                o[c + 1] = make_float2(cum + SEPF * (float)(c + 1), xc);
            }
            o[NCOMP].x = fmaxf(o[NCOMP - 1].x + SEPF, T1F);
            float2* op = reinterpret_cast<float2*>(out + (size_t)(row0 + rp + 8) * 2 * (NCOMP + 1));
            #pragma unroll
            for (int j2 = 0; j2 < NCOMP + 1; j2++) op[j2] = o[j2];
        }
    }
}

extern "C" void kernel_launch(void* const* d_in, const int* in_sizes, int n_in,
                              void* d_out, int out_size)
{
    const float* B    = (const float*)d_in[0];
    const float* Bcat = (const float*)d_in[1];
    const float* Wh   = (const float*)d_in[2];
    const float* Whc  = (const float*)d_in[3];
    const float* bh   = (const float*)d_in[4];
    const float* Wv   = (const float*)d_in[5];
    const float* Wvc  = (const float*)d_in[6];
    const float* bv   = (const float*)d_in[7];
    const float* Wic  = (const float*)d_in[8];
    const float* Wicc = (const float*)d_in[9];
    const float* bic  = (const float*)d_in[10];
    float* out = (float*)d_out;

    const size_t smem = SMEM_F * sizeof(float);   // 45,056 B (< 48 KB, no attribute needed)
    k_main<<<BATCH / RPB, TPB, smem>>>(B, Bcat, Wh, bh, Wv, bv, Wic, bic,
                                       Whc, Wvc, Wicc, out);
}